// round 2
// baseline (speedup 1.0000x reference)
#include <cuda_runtime.h>
#include <math.h>

#define NEXP 16
#define MAX_T 4096

// Scratch (allocation-free per harness rules)
__device__ float g_probs[MAX_T * NEXP];
__device__ float g_s0[MAX_T];
__device__ float g_s1[MAX_T];
__device__ int   g_i0[MAX_T];
__device__ int   g_i1[MAX_T];

// ---------------------------------------------------------------------------
// Kernel 1: gating. One warp per token: 16 dot products of length H,
// warp-shuffle reduce, lane 0 does softmax + top-2 + renormalize.
// gate_w (16*H*4 = 131KB) stays resident in L2 across all tokens.
// ---------------------------------------------------------------------------
__global__ void gate_kernel(const float* __restrict__ hs,
                            const float* __restrict__ gw,
                            int T, int H) {
    int warp = (blockIdx.x * blockDim.x + threadIdx.x) >> 5;
    int lane = threadIdx.x & 31;
    if (warp >= T) return;

    const float* hrow = hs + (size_t)warp * H;
    float acc[NEXP];
#pragma unroll
    for (int e = 0; e < NEXP; e++) acc[e] = 0.f;

    for (int h = lane; h < H; h += 32) {
        float hv = hrow[h];
#pragma unroll
        for (int e = 0; e < NEXP; e++)
            acc[e] = fmaf(hv, __ldg(&gw[e * H + h]), acc[e]);
    }

#pragma unroll
    for (int e = 0; e < NEXP; e++) {
#pragma unroll
        for (int off = 16; off; off >>= 1)
            acc[e] += __shfl_xor_sync(0xffffffffu, acc[e], off);
    }

    if (lane == 0) {
        // softmax over 16 logits
        float m = acc[0];
#pragma unroll
        for (int e = 1; e < NEXP; e++) m = fmaxf(m, acc[e]);
        float p[NEXP];
        float sum = 0.f;
#pragma unroll
        for (int e = 0; e < NEXP; e++) { p[e] = __expf(acc[e] - m); sum += p[e]; }
        float inv = 1.f / sum;
#pragma unroll
        for (int e = 0; e < NEXP; e++) {
            p[e] *= inv;
            g_probs[warp * NEXP + e] = p[e];
        }
        // top-2 (first index wins ties, matching lax.top_k)
        float b0 = -1.f, b1 = -1.f;
        int   bi0 = 0,   bi1 = 0;
#pragma unroll
        for (int e = 0; e < NEXP; e++) {
            if (p[e] > b0)      { b1 = b0; bi1 = bi0; b0 = p[e]; bi0 = e; }
            else if (p[e] > b1) { b1 = p[e]; bi1 = e; }
        }
        float s = 1.f / (b0 + b1);
        g_s0[warp] = b0 * s;
        g_s1[warp] = b1 * s;
        g_i0[warp] = bi0;
        g_i1[warp] = bi1;
    }
}

// ---------------------------------------------------------------------------
// Kernel 2: bias = s0*eb[i0] + s1*eb[i1], per token, float4 vectorized.
// Output (262MB) is the bottleneck -> streaming stores so expert_biases
// (2MB) stays L2-resident.
// ---------------------------------------------------------------------------
__global__ void bias_kernel(const float* __restrict__ eb,
                            float* __restrict__ out,
                            int V) {
    int t  = blockIdx.y;
    int v4 = blockIdx.x * blockDim.x + threadIdx.x;
    int V4 = V >> 2;
    if (v4 >= V4) return;

    float s0 = g_s0[t];
    float s1 = g_s1[t];
    const float4* e0 = (const float4*)(eb + (size_t)g_i0[t] * V);
    const float4* e1 = (const float4*)(eb + (size_t)g_i1[t] * V);

    float4 a = __ldg(&e0[v4]);
    float4 b = __ldg(&e1[v4]);
    float4 r;
    r.x = fmaf(s0, a.x, s1 * b.x);
    r.y = fmaf(s0, a.y, s1 * b.y);
    r.z = fmaf(s0, a.z, s1 * b.z);
    r.w = fmaf(s0, a.w, s1 * b.w);

    float4* o = (float4*)(out + (size_t)t * V);
    __stcs(&o[v4], r);
}

// ---------------------------------------------------------------------------
// Kernel 3: aux loss. Deterministic reduction (no float atomics):
// one warp per expert sums probs over tokens; thread 0 finishes.
// ---------------------------------------------------------------------------
__global__ void aux_kernel(float* __restrict__ out_aux, int T) {
    __shared__ float su[NEXP];
    int e    = threadIdx.x >> 5;   // 16 warps, 512 threads
    int lane = threadIdx.x & 31;

    float s = 0.f;
    for (int t = lane; t < T; t += 32)
        s += g_probs[t * NEXP + e];
#pragma unroll
    for (int off = 16; off; off >>= 1)
        s += __shfl_xor_sync(0xffffffffu, s, off);
    if (lane == 0) su[e] = s / (float)T;
    __syncthreads();

    if (threadIdx.x == 0) {
        float a = 0.f;
#pragma unroll
        for (int i = 0; i < NEXP; i++)
            a += su[i] * logf(su[i]);
        *out_aux = a * (float)NEXP;
    }
}

extern "C" void kernel_launch(void* const* d_in, const int* in_sizes, int n_in,
                              void* d_out, int out_size) {
    const float* hs = (const float*)d_in[0];  // (T, H)
    const float* gw = (const float*)d_in[1];  // (E, H)
    const float* eb = (const float*)d_in[2];  // (E, V)
    float* out = (float*)d_out;

    int H = in_sizes[1] / NEXP;
    int T = in_sizes[0] / H;
    int V = in_sizes[2] / NEXP;

    // 1. gating: one warp per token
    int threads = 256;
    int blocks = (T * 32 + threads - 1) / threads;
    gate_kernel<<<blocks, threads>>>(hs, gw, T, H);

    // 2. bias: grid (V/4 per 256 threads) x T
    int V4 = V >> 2;
    dim3 grid((V4 + 255) / 256, T);
    bias_kernel<<<grid, 256>>>(eb, out, V);

    // 3. aux loss appended after bias if the output buffer has room
    long long tv = (long long)T * (long long)V;
    if ((long long)out_size > tv) {
        aux_kernel<<<1, 512>>>(out + tv, T);
    }
}